// round 1
// baseline (speedup 1.0000x reference)
#include <cuda_runtime.h>
#include <math.h>

#define GG 13
#define AA 5
#define CC 36
#define TT 30
#define BB 1024
#define GSQ (GG*GG)                 // 169
#define CELLS_PER_B (AA*GSQ)        // 845
#define N_TOTAL (BB*CELLS_PER_B)    // 865280
#define CH (5+CC)                   // 41

__device__ int    d_winner[N_TOTAL];
__device__ double d_accum[3];   // coord, conf, class

__constant__ float c_aw[AA] = {1.08f, 3.42f, 6.63f, 9.42f, 16.62f};
__constant__ float c_ah[AA] = {1.19f, 4.41f, 11.38f, 5.11f, 10.52f};

// ---------------------------------------------------------------------------
// Reset scratch state (runs every launch; deterministic)
// ---------------------------------------------------------------------------
__global__ void init_kernel() {
    int i = blockIdx.x * blockDim.x + threadIdx.x;
    if (i < N_TOTAL) d_winner[i] = -1;
    if (i < 3) d_accum[i] = 0.0;
}

// ---------------------------------------------------------------------------
// Build targets: one thread per batch, serial over T targets (last-wins order,
// min-class for one-hot collisions).
// ---------------------------------------------------------------------------
__global__ void build_targets_kernel(const float* __restrict__ target) {
    int b = blockIdx.x * blockDim.x + threadIdx.x;
    if (b >= BB) return;
    const float* tb = target + (long long)b * TT * 5;
    for (int t = 0; t < TT; ++t) {
        float x  = tb[t*5 + 0];
        float y  = tb[t*5 + 1];
        float w  = tb[t*5 + 2];
        float h  = tb[t*5 + 3];
        float cl = tb[t*5 + 4];
        if (x + y + w + h + cl == 0.0f) continue;   // invalid (dropped)
        float gx = x * GG, gy = y * GG, gw = w * GG, gh = h * GG;
        int gi = (int)gx;
        int gj = (int)gy;
        float best = -1.0f;
        int bn = 0;
        #pragma unroll
        for (int a = 0; a < AA; ++a) {
            float inter = fminf(gw, c_aw[a]) * fminf(gh, c_ah[a]);
            float uni   = gw * gh + c_aw[a] * c_ah[a] - inter;
            float iou   = inter / (uni + 1e-16f);
            if (iou > best) { best = iou; bn = a; }   // strict > => first max (argmax semantics)
        }
        int n = ((b * AA + bn) * GG + gj) * GG + gi;
        int cls = (int)cl;
        int old = d_winner[n];
        if (old >= 0) {
            int oc = old & 0xFFFF;
            if (oc < cls) cls = oc;                   // min-class on collision
        }
        d_winner[n] = (t << 16) | cls;                // last target wins for coords
    }
}

// ---------------------------------------------------------------------------
// Main pass: one thread per cell.
// ---------------------------------------------------------------------------
__global__ __launch_bounds__(256)
void loss_kernel(const float* __restrict__ pred, const float* __restrict__ target) {
    int n = blockIdx.x * blockDim.x + threadIdx.x;

    double acc_coord = 0.0, acc_conf = 0.0, acc_class = 0.0;

    if (n < N_TOTAL) {
        int b = n / CELLS_PER_B;
        int r = n - b * CELLS_PER_B;
        int a = r / GSQ;
        int s = r - a * GSQ;                       // gj*13 + gi

        const float* base = pred + ((long long)(b * AA + a) * CH) * GSQ + s;

        int w = d_winner[n];
        int label = (w >= 0) ? (w & 0xFFFF) : 0;

        // conf channel
        float x0 = __ldg(base);
        float sg = 1.0f / (1.0f + __expf(-x0));

        // class channels 5..40: max + select label value
        float v[CC];
        float m = -INFINITY;
        float xlab = 0.0f;
        #pragma unroll
        for (int c = 0; c < CC; ++c) {
            v[c] = __ldg(base + (5 + c) * GSQ);
            m = fmaxf(m, v[c]);
            if (c == label) xlab = v[c];
        }
        float S = 0.0f;
        #pragma unroll
        for (int c = 0; c < CC; ++c) S += __expf(v[c] - m);
        acc_class = (double)(m + __logf(S) - xlab);

        if (w >= 0) {
            // target cell: conf term with OBJ_SCALE, plus coord term
            float e = 5.0f * (sg - 1.0f);
            acc_conf = (double)(e * e);

            int t = w >> 16;
            const float* tb = target + ((long long)b * TT + t) * 5;
            float gx = tb[0] * GG, gy = tb[1] * GG, gw = tb[2] * GG, gh = tb[3] * GG;
            int gi = (int)gx;
            int gj = (int)gy;
            float best = -1.0f; int bn = 0;
            #pragma unroll
            for (int aa = 0; aa < AA; ++aa) {
                float inter = fminf(gw, c_aw[aa]) * fminf(gh, c_ah[aa]);
                float uni   = gw * gh + c_aw[aa] * c_ah[aa] - inter;
                float iou   = inter / (uni + 1e-16f);
                if (iou > best) { best = iou; bn = aa; }
            }
            float tx = gx - (float)gi;
            float ty = gy - (float)gj;
            float tw = __logf(gw / c_aw[bn] + 1e-16f);
            float th = __logf(gh / c_ah[bn] + 1e-16f);

            float p1 = __ldg(base + 1 * GSQ);
            float p2 = __ldg(base + 2 * GSQ);
            float p3 = __ldg(base + 3 * GSQ);
            float p4 = __ldg(base + 4 * GSQ);
            float d1 = p1 - tx, d2 = p2 - ty, d3 = p3 - tw, d4 = p4 - th;
            acc_coord = (double)(d1*d1 + d2*d2 + d3*d3 + d4*d4);
        } else {
            acc_conf = (double)(sg * sg);
        }
    }

    // warp reduce
    #pragma unroll
    for (int off = 16; off > 0; off >>= 1) {
        acc_coord += __shfl_down_sync(0xFFFFFFFF, acc_coord, off);
        acc_conf  += __shfl_down_sync(0xFFFFFFFF, acc_conf,  off);
        acc_class += __shfl_down_sync(0xFFFFFFFF, acc_class, off);
    }

    __shared__ double sh[3][8];
    int warp = threadIdx.x >> 5;
    int lane = threadIdx.x & 31;
    if (lane == 0) {
        sh[0][warp] = acc_coord;
        sh[1][warp] = acc_conf;
        sh[2][warp] = acc_class;
    }
    __syncthreads();
    if (warp == 0) {
        double c0 = (lane < 8) ? sh[0][lane] : 0.0;
        double c1 = (lane < 8) ? sh[1][lane] : 0.0;
        double c2 = (lane < 8) ? sh[2][lane] : 0.0;
        #pragma unroll
        for (int off = 4; off > 0; off >>= 1) {
            c0 += __shfl_down_sync(0xFFFFFFFF, c0, off);
            c1 += __shfl_down_sync(0xFFFFFFFF, c1, off);
            c2 += __shfl_down_sync(0xFFFFFFFF, c2, off);
        }
        if (lane == 0) {
            atomicAdd(&d_accum[0], c0);
            atomicAdd(&d_accum[1], c1);
            atomicAdd(&d_accum[2], c2);
        }
    }
}

// ---------------------------------------------------------------------------
// Finalize: divide by B, write (total, coord, conf, class)
// ---------------------------------------------------------------------------
__global__ void finalize_kernel(float* __restrict__ out) {
    double coord = d_accum[0] / (double)BB;
    double conf  = d_accum[1] / (double)BB;
    double cls   = d_accum[2] / (double)BB;
    out[0] = (float)(coord + conf + cls);
    out[1] = (float)coord;
    out[2] = (float)conf;
    out[3] = (float)cls;
}

extern "C" void kernel_launch(void* const* d_in, const int* in_sizes, int n_in,
                              void* d_out, int out_size) {
    const float* pred   = (const float*)d_in[0];
    const float* target = (const float*)d_in[1];
    float* out = (float*)d_out;

    init_kernel<<<(N_TOTAL + 255) / 256, 256>>>();
    build_targets_kernel<<<(BB + 255) / 256, 256>>>(target);
    loss_kernel<<<(N_TOTAL + 255) / 256, 256>>>(pred, target);
    finalize_kernel<<<1, 1>>>(out);
}